// round 4
// baseline (speedup 1.0000x reference)
#include <cuda_runtime.h>

// Problem constants
#define N_ROWS 8192
#define DIM    128
#define CBK    16384
#define TOPK   3
#define TAU    0.01f

// Tiling
#define BM      64          // rows per block
#define BC      128         // codebook cols per chunk
#define NCHUNK  (CBK / BC)  // 128
#define THREADS 256
#define TM      4           // rows per thread
#define TN      8           // cols per thread

// Dynamic smem layout (floats): x[8192] | cb0[16384] | cb1[16384]
#define SMEM_FLOATS (8192 + 2 * 16384)

// Scratch for codebook column sums (no cudaMalloc allowed)
__device__ float g_Spart[128 * DIM];
__device__ float g_S[DIM];

// ---------------------------------------------------------------------------
// S = column sums of codebook (two deterministic kernels, no atomics)
// ---------------------------------------------------------------------------
__global__ void colsum_part(const float* __restrict__ cb) {
    int b = blockIdx.x;        // 128 blocks, 128 rows each
    int d = threadIdx.x;       // 128 threads = one per column
    const float* p = cb + (size_t)b * 128 * DIM + d;
    float s = 0.0f;
#pragma unroll 8
    for (int r = 0; r < 128; ++r) s += p[r * DIM];
    g_Spart[b * DIM + d] = s;
}

__global__ void colsum_final() {
    int d = threadIdx.x;
    float s = 0.0f;
#pragma unroll 8
    for (int b = 0; b < 128; ++b) s += g_Spart[b * DIM + d];
    g_S[d] = s;
}

// ---------------------------------------------------------------------------
// Packed f32x2 FMA (Blackwell): d.lo += a.lo*b.lo ; d.hi += a.hi*b.hi
// ---------------------------------------------------------------------------
__device__ __forceinline__ unsigned long long ffma2(
    unsigned long long a, unsigned long long b, unsigned long long c) {
    unsigned long long d;
    asm("fma.rn.f32x2 %0, %1, %2, %3;" : "=l"(d) : "l"(a), "l"(b), "l"(c));
    return d;
}

// ---------------------------------------------------------------------------
// Main fused kernel: scores GEMM + running top-3 + softmax epilogue
// ---------------------------------------------------------------------------
__global__ void __launch_bounds__(THREADS, 1)
metoken_main(const float* __restrict__ x,
             const float* __restrict__ cb,
             float* __restrict__ out) {
    extern __shared__ float sm[];
    float* x_sh = sm;
    float* cbbuf0 = sm + 8192;
    float* cbbuf1 = sm + 8192 + 16384;

    const int tid  = threadIdx.x;
    const int tx   = tid & 15;      // col group: cols tx*8 .. tx*8+7
    const int ty   = tid >> 4;      // row group: rows ty*4 .. ty*4+3
    const int r0   = ty * TM;
    const int row0 = blockIdx.x * BM;
    const int sw   = tx & 7;        // swizzle key for this thread's cb reads

    // ---- load x tile (64x128) into shared, plain float4 ----
    {
        const float4* xg = reinterpret_cast<const float4*>(x + (size_t)row0 * DIM);
        float4* xs = reinterpret_cast<float4*>(x_sh);
#pragma unroll
        for (int t = 0; t < 8; ++t) {
            int idx = tid + t * THREADS;   // 2048 float4 total
            xs[idx] = xg[idx];
        }
    }

    // ---- cp.async producer for one cb chunk (BC x DIM), XOR-swizzled ----
    auto issue_chunk = [&](int chunk, float* buf) {
        const float* src = cb + (size_t)chunk * BC * DIM;
        unsigned int dstbase = (unsigned int)__cvta_generic_to_shared(buf);
#pragma unroll
        for (int t = 0; t < 16; ++t) {
            int idx = tid + t * THREADS;   // 4096 float4 total
            int c = idx >> 5;              // cb row (column of scores)
            int q = idx & 31;              // 16B chunk along D
            int s = (c >> 3) & 7;
            unsigned int dst = dstbase +
                (unsigned int)((c * DIM + ((q ^ s) << 2)) * 4);
            const float* srcp = src + c * DIM + (q << 2);
            asm volatile("cp.async.cg.shared.global [%0], [%1], 16;"
                         :: "r"(dst), "l"(srcp));
        }
        asm volatile("cp.async.commit_group;" ::: "memory");
    };

    issue_chunk(0, cbbuf0);

    // ---- per-thread running top-3 for TM rows ----
    float t0[TM], t1[TM], t2[TM];
    int   j0[TM], j1[TM], j2[TM];
#pragma unroll
    for (int r = 0; r < TM; ++r) {
        t0[r] = t1[r] = t2[r] = -3.4e38f;
        j0[r] = j1[r] = j2[r] = 0;
    }

    for (int chunk = 0; chunk < NCHUNK; ++chunk) {
        float* cur = (chunk & 1) ? cbbuf1 : cbbuf0;
        if (chunk + 1 < NCHUNK) {
            issue_chunk(chunk + 1, (chunk & 1) ? cbbuf0 : cbbuf1);
            asm volatile("cp.async.wait_group 1;" ::: "memory");
        } else {
            asm volatile("cp.async.wait_group 0;" ::: "memory");
        }
        __syncthreads();

        // f32x2 accumulators: lo = even-k partial, hi = odd-k partial
        unsigned long long acc[TM][TN];
#pragma unroll
        for (int r = 0; r < TM; ++r)
#pragma unroll
            for (int c = 0; c < TN; ++c) acc[r][c] = 0ull;

#pragma unroll 4
        for (int q = 0; q < 32; ++q) {
            ulonglong2 xa[TM];
#pragma unroll
            for (int r = 0; r < TM; ++r)
                xa[r] = *reinterpret_cast<const ulonglong2*>(
                    x_sh + (r0 + r) * DIM + (q << 2));
#pragma unroll
            for (int c = 0; c < TN; ++c) {
                ulonglong2 b = *reinterpret_cast<const ulonglong2*>(
                    cur + (tx * TN + c) * DIM + ((q ^ sw) << 2));
#pragma unroll
                for (int r = 0; r < TM; ++r) {
                    acc[r][c] = ffma2(xa[r].x, b.x, acc[r][c]);
                    acc[r][c] = ffma2(xa[r].y, b.y, acc[r][c]);
                }
            }
        }

        // fold pairs and update top-3
#pragma unroll
        for (int c = 0; c < TN; ++c) {
            int gidx = chunk * BC + tx * TN + c;
#pragma unroll
            for (int r = 0; r < TM; ++r) {
                float lo = __uint_as_float((unsigned int)(acc[r][c] & 0xffffffffull));
                float hi = __uint_as_float((unsigned int)(acc[r][c] >> 32));
                float s = lo + hi;
                if (s > t2[r]) {
                    if (s > t1[r]) {
                        t2[r] = t1[r]; j2[r] = j1[r];
                        if (s > t0[r]) {
                            t1[r] = t0[r]; j1[r] = j0[r];
                            t0[r] = s;     j0[r] = gidx;
                        } else { t1[r] = s; j1[r] = gidx; }
                    } else { t2[r] = s; j2[r] = gidx; }
                }
            }
        }
        __syncthreads();   // protect 'cur' before next iteration's cp.async overwrite
    }

    // ---- cross-thread top-3 merge (overlay on cbbuf0, which is now dead) ----
    float* redv  = cbbuf0;                                 // 64*16*3 = 3072
    int*   redi  = reinterpret_cast<int*>(cbbuf0 + 3072);  // 3072
    float* rcoef = cbbuf0 + 6144;                          // 64 * 8

#pragma unroll
    for (int r = 0; r < TM; ++r) {
        int base = ((r0 + r) * 16 + tx) * 3;
        redv[base + 0] = t0[r]; redv[base + 1] = t1[r]; redv[base + 2] = t2[r];
        redi[base + 0] = j0[r]; redi[base + 1] = j1[r]; redi[base + 2] = j2[r];
    }
    __syncthreads();

    if (tid < BM) {
        float v0 = -3.4e38f, v1 = -3.4e38f, v2 = -3.4e38f;
        int   i0 = 0, i1 = 0, i2 = 0;
        for (int t = 0; t < 48; ++t) {
            float s = redv[tid * 48 + t];
            int   g = redi[tid * 48 + t];
            if (s > v2) {
                if (s > v1) {
                    v2 = v1; i2 = i1;
                    if (s > v0) { v1 = v0; i1 = i0; v0 = s; i0 = g; }
                    else        { v1 = s;  i1 = g; }
                } else { v2 = s; i2 = g; }
            }
        }
        // softmax closed form (same fp32 recipe as jax: subtract running max)
        float a0 = v0 / TAU, a1 = v1 / TAU, a2 = v2 / TAU;
        float M  = fmaxf(a0, 0.0f);
        float w0 = expf(a0 - M), w1 = expf(a1 - M), w2 = expf(a2 - M);
        float e  = expf(-M);
        float Z  = w0 + w1 + w2 + (float)(CBK - TOPK) * e;
        float inv = 1.0f / Z;
        rcoef[tid * 8 + 0] = (w0 - e) * inv;
        rcoef[tid * 8 + 1] = (w1 - e) * inv;
        rcoef[tid * 8 + 2] = (w2 - e) * inv;
        rcoef[tid * 8 + 3] = e * inv;
        reinterpret_cast<int*>(rcoef)[tid * 8 + 4] = i0;
        reinterpret_cast<int*>(rcoef)[tid * 8 + 5] = i1;
        reinterpret_cast<int*>(rcoef)[tid * 8 + 6] = i2;
    }
    __syncthreads();

    // ---- epilogue: z_q = c0*cb[i0] + c1*cb[i1] + c2*cb[i2] + ce*S ----
    for (int eidx = tid; eidx < BM * DIM; eidx += THREADS) {
        int r = eidx >> 7;      // local row
        int d = eidx & 127;     // column
        const float* rc = rcoef + r * 8;
        int i0 = reinterpret_cast<const int*>(rc)[4];
        int i1 = reinterpret_cast<const int*>(rc)[5];
        int i2 = reinterpret_cast<const int*>(rc)[6];
        float val = rc[0] * cb[i0 * DIM + d]
                  + rc[1] * cb[i1 * DIM + d]
                  + rc[2] * cb[i2 * DIM + d]
                  + rc[3] * g_S[d];
        out[(size_t)(row0 + r) * DIM + d] = val;
    }
}

// ---------------------------------------------------------------------------
// Launch
// ---------------------------------------------------------------------------
extern "C" void kernel_launch(void* const* d_in, const int* in_sizes, int n_in,
                              void* d_out, int out_size) {
    const float* x  = (const float*)d_in[0];   // [8192, 128]
    const float* cb = (const float*)d_in[1];   // [16384, 128]
    float* out = (float*)d_out;                // [8192, 128]

    colsum_part<<<128, 128>>>(cb);
    colsum_final<<<1, 128>>>();

    size_t smem_bytes = SMEM_FLOATS * sizeof(float);   // 160 KB
    cudaFuncSetAttribute(metoken_main,
                         cudaFuncAttributeMaxDynamicSharedMemorySize,
                         (int)smem_bytes);
    metoken_main<<<N_ROWS / BM, THREADS, smem_bytes>>>(x, cb, out);
}

// round 9
// speedup vs baseline: 1.9940x; 1.9940x over previous
#include <cuda_runtime.h>
#include <cuda_bf16.h>
#include <cstdint>

// ---------------- problem constants ----------------
#define N_ROWS 8192
#define DIM    128
#define CBK    16384
#define TAU    0.01f

#define BM     64            // rows per CTA
#define NT     128           // col tiles (16384 / 128)
#define TILE_N 128

// smem layout (bytes)
#define XS_OFF 0             // 64 x 256B  = 16384
#define CB_OFF 16384         // 2 x 32768  = 65536
#define SC_OFF 81920         // 64 x 512B  = 32768
#define SM_TOTAL 114688

// ---------------- device scratch (no cudaMalloc allowed) ----------------
__device__ __nv_bfloat16 g_xh[(size_t)N_ROWS * DIM];
__device__ __nv_bfloat16 g_cbh[(size_t)CBK * DIM];
__device__ float g_Spart[128 * DIM];
__device__ float g_S[DIM];
__device__ int   g_candi[(size_t)N_ROWS * 32];

// ---------------- helpers ----------------
__device__ __forceinline__ uint32_t smem_u32(const void* p) {
    uint32_t a;
    asm("{ .reg .u64 t; cvta.to.shared.u64 t, %1; cvt.u32.u64 %0, t; }" : "=r"(a) : "l"(p));
    return a;
}
__device__ __forceinline__ void cp16(uint32_t dst, const void* src) {
    asm volatile("cp.async.cg.shared.global [%0], [%1], 16;" :: "r"(dst), "l"(src));
}
#define CP_COMMIT() asm volatile("cp.async.commit_group;" ::: "memory")
#define CP_WAIT1()  asm volatile("cp.async.wait_group 1;" ::: "memory")
#define CP_WAIT0()  asm volatile("cp.async.wait_group 0;" ::: "memory")

__device__ __forceinline__ void ldsm_x4(uint32_t* r, uint32_t addr) {
    asm volatile("ldmatrix.sync.aligned.m8n8.x4.shared.b16 {%0,%1,%2,%3}, [%4];"
                 : "=r"(r[0]), "=r"(r[1]), "=r"(r[2]), "=r"(r[3]) : "r"(addr));
}
__device__ __forceinline__ void mma_bf16(float* c, const uint32_t* a, const uint32_t* b) {
    asm volatile(
        "mma.sync.aligned.m16n8k16.row.col.f32.bf16.bf16.f32 "
        "{%0,%1,%2,%3}, {%4,%5,%6,%7}, {%8,%9}, {%0,%1,%2,%3};"
        : "+f"(c[0]), "+f"(c[1]), "+f"(c[2]), "+f"(c[3])
        : "r"(a[0]), "r"(a[1]), "r"(a[2]), "r"(a[3]), "r"(b[0]), "r"(b[1]));
}

// ---------------------------------------------------------------------------
// prep: bf16 casts + codebook column sums
// ---------------------------------------------------------------------------
__global__ void __launch_bounds__(256) prep_cb(const float* __restrict__ cb) {
    int b = blockIdx.x;                 // 128 blocks x 128 rows
    int tid = threadIdx.x;
    const float* src = cb + (size_t)b * 128 * DIM;
    for (int e = tid; e < 128 * DIM; e += 256)
        g_cbh[(size_t)b * 128 * DIM + e] = __float2bfloat16(src[e]);
    __shared__ float ssum[256];
    int d = tid & 127, half = tid >> 7;
    float s = 0.0f;
#pragma unroll 8
    for (int r = half * 64; r < half * 64 + 64; ++r) s += src[r * DIM + d];
    ssum[tid] = s;
    __syncthreads();
    if (tid < 128) g_Spart[b * DIM + tid] = ssum[tid] + ssum[128 + tid];
}

__global__ void __launch_bounds__(256) prep_x(const float* __restrict__ x) {
    size_t base = (size_t)blockIdx.x * 128 * DIM;   // 64 blocks x 128 rows
    for (int e = threadIdx.x; e < 128 * DIM; e += 256)
        g_xh[base + e] = __float2bfloat16(x[base + e]);
}

__global__ void colsum_final() {
    int d = threadIdx.x;
    float s = 0.0f;
#pragma unroll 8
    for (int b = 0; b < 128; ++b) s += g_Spart[b * DIM + d];
    g_S[d] = s;
}

// ---------------------------------------------------------------------------
// cb tile loader: 2048 x 16B chunks, XOR-swizzled rows (256B/row)
// ---------------------------------------------------------------------------
__device__ __forceinline__ void load_cb_tile(int tile, int buf, int tid, uint32_t sbase) {
    const __nv_bfloat16* src0 = g_cbh + (size_t)tile * TILE_N * DIM;
    uint32_t dst0 = sbase + CB_OFF + (uint32_t)buf * 32768u;
#pragma unroll
    for (int k = 0; k < 8; ++k) {
        int c = tid + k * 256;          // 0..2047
        int n = c >> 4, kc = c & 15;
        cp16(dst0 + (uint32_t)(n * 256 + (((kc ^ (n & 7))) << 4)),
             src0 + (size_t)n * DIM + kc * 8);
    }
}

// ---------------------------------------------------------------------------
// main: bf16 mma.sync scores GEMM + guaranteed top-8 candidates per row
// ---------------------------------------------------------------------------
__global__ void __launch_bounds__(256, 1) metoken_mma() {
    extern __shared__ char smem[];
    uint32_t sbase = smem_u32(smem);
    float* scores = reinterpret_cast<float*>(smem + SC_OFF);

    const int tid = threadIdx.x, warp = tid >> 5, lane = tid & 31;
    const int wm = warp >> 2, wn = warp & 3;
    const int rowbase = blockIdx.x * BM;

    // ---- prologue loads: x tile + first two cb tiles ----
#pragma unroll
    for (int k = 0; k < 4; ++k) {
        int c = tid + k * 256;          // 0..1023
        int r = c >> 4, kc = c & 15;
        cp16(sbase + XS_OFF + (uint32_t)(r * 256 + ((kc ^ (r & 7)) << 4)),
             g_xh + (size_t)(rowbase + r) * DIM + kc * 8);
    }
    CP_COMMIT();
    load_cb_tile(0, 0, tid, sbase); CP_COMMIT();
    load_cb_tile(1, 1, tid, sbase); CP_COMMIT();
    CP_WAIT1();                          // xs + tile0 arrived
    __syncthreads();

    // ---- hoist A fragments for the whole kernel (K=128, M=32 per warp) ----
    const int arow0 = wm * 32 + ((lane >> 3) & 1) * 8 + (lane & 7);
    const int ahi   = (lane >> 4) & 1;
    const int swa   = arow0 & 7;
    uint32_t ra[2][8][4];
#pragma unroll
    for (int mt = 0; mt < 2; ++mt)
#pragma unroll
        for (int kt = 0; kt < 8; ++kt)
            ldsm_x4(ra[mt][kt],
                    sbase + XS_OFF + (uint32_t)((arow0 + mt * 16) * 256 +
                                                (((kt * 2 + ahi) ^ swa) << 4)));

    // B lane constants
    const int bn0 = wn * 32 + ((lane >> 4) & 1) * 8 + (lane & 7);
    const int bhi = (lane >> 3) & 1;
    const int swb = bn0 & 7;

    // per-thread sorted top-8
    float v[8]; int ix[8];
#pragma unroll
    for (int k = 0; k < 8; ++k) { v[k] = -3.4e38f; ix[k] = 0; }

    const int srow = tid & 63, q = tid >> 6;
    const int swl  = (srow & 15) << 1;
    const float* srp = scores + srow * 128 + q * 32;

    for (int i = 0; i < NT; ++i) {
        if (i == NT - 1) { CP_WAIT0(); } else if (i > 0) { CP_WAIT1(); }
        __syncthreads();                 // cb[i%2] visible; scan(i-1) done

        uint32_t cbb = sbase + CB_OFF + (uint32_t)(i & 1) * 32768u;
        float acc[2][4][4];
#pragma unroll
        for (int mt = 0; mt < 2; ++mt)
#pragma unroll
            for (int nt = 0; nt < 4; ++nt)
#pragma unroll
                for (int e = 0; e < 4; ++e) acc[mt][nt][e] = 0.0f;

#pragma unroll
        for (int kt = 0; kt < 8; ++kt) {
            uint32_t rb[2][4];
#pragma unroll
            for (int g = 0; g < 2; ++g)
                ldsm_x4(rb[g], cbb + (uint32_t)((bn0 + g * 16) * 256 +
                                                (((kt * 2 + bhi) ^ swb) << 4)));
#pragma unroll
            for (int nt = 0; nt < 4; ++nt) {
                const uint32_t* bf = &rb[nt >> 1][(nt & 1) * 2];
#pragma unroll
                for (int mt = 0; mt < 2; ++mt)
                    mma_bf16(acc[mt][nt], ra[mt][kt], bf);
            }
        }

        // ---- store scores to swizzled smem ----
#pragma unroll
        for (int mt = 0; mt < 2; ++mt) {
            int rlo = wm * 32 + mt * 16 + (lane >> 2);
            int rhi = rlo + 8;
#pragma unroll
            for (int nt = 0; nt < 4; ++nt) {
                int col = wn * 32 + nt * 8 + 2 * (lane & 3);
                int plo = col ^ ((rlo & 15) << 1);
                int phi = col ^ ((rhi & 15) << 1);
                *reinterpret_cast<float2*>(&scores[rlo * 128 + plo]) =
                    make_float2(acc[mt][nt][0], acc[mt][nt][1]);
                *reinterpret_cast<float2*>(&scores[rhi * 128 + phi]) =
                    make_float2(acc[mt][nt][2], acc[mt][nt][3]);
            }
        }
        __syncthreads();                 // scores visible; cb[i%2] reads done

        if (i + 2 < NT) { load_cb_tile(i + 2, i & 1, tid, sbase); CP_COMMIT(); }

        // ---- scan 32 cols of my row, maintain sorted top-8 ----
#pragma unroll 8
        for (int jj = 0; jj < 32; ++jj) {
            float s = srp[jj];
            if (s > v[7]) {
                v[7] = s;
                ix[7] = i * 128 + ((q * 32 + jj) ^ swl);
#pragma unroll
                for (int p = 7; p > 0; --p) {
                    if (v[p] > v[p - 1]) {
                        float tv = v[p - 1]; v[p - 1] = v[p]; v[p] = tv;
                        int ti = ix[p - 1]; ix[p - 1] = ix[p]; ix[p] = ti;
                    }
                }
            }
        }
    }

    // ---- emit 8 candidates per (row, quarter): 32 per row total ----
#pragma unroll
    for (int k = 0; k < 8; ++k)
        g_candi[(size_t)(rowbase + srow) * 32 + q * 8 + k] = ix[k];
}

// ---------------------------------------------------------------------------
// epilogue: exact fp32 rescore of 32 candidates, top-3, closed-form softmax
// ---------------------------------------------------------------------------
__global__ void __launch_bounds__(128) epilogue(const float* __restrict__ x,
                                                const float* __restrict__ cb,
                                                float* __restrict__ out) {
    int row = blockIdx.x;
    int d = threadIdx.x, wid = d >> 5, lane = d & 31;
    __shared__ int   cands[32];
    __shared__ float sred[32][4];
    __shared__ float ssc[32];
    __shared__ float scoef[4];
    __shared__ int   sidx[3];

    if (d < 32) cands[d] = g_candi[(size_t)row * 32 + d];
    __syncthreads();

    float xd = x[(size_t)row * DIM + d];
#pragma unroll
    for (int j = 0; j < 32; ++j) {
        float p = xd * cb[(size_t)cands[j] * DIM + d];
#pragma unroll
        for (int o = 16; o > 0; o >>= 1) p += __shfl_xor_sync(0xffffffff, p, o);
        if (lane == 0) sred[j][wid] = p;
    }
    __syncthreads();
    if (d < 32) ssc[d] = sred[d][0] + sred[d][1] + sred[d][2] + sred[d][3];
    __syncthreads();
    if (d == 0) {
        float b0 = -3.4e38f, b1 = -3.4e38f, b2 = -3.4e38f;
        int   o0 = 0, o1 = 0, o2 = 0;
        for (int j = 0; j < 32; ++j) {
            float s = ssc[j];
            if (s > b2) {
                if (s > b1) {
                    b2 = b1; o2 = o1;
                    if (s > b0) { b1 = b0; o1 = o0; b0 = s; o0 = j; }
                    else        { b1 = s;  o1 = j; }
                } else { b2 = s; o2 = j; }
            }
        }
        float a0 = b0 / TAU, a1 = b1 / TAU, a2 = b2 / TAU;
        float M  = fmaxf(a0, 0.0f);
        float w0 = expf(a0 - M), w1 = expf(a1 - M), w2 = expf(a2 - M);
        float e  = expf(-M);
        float Z  = w0 + w1 + w2 + (float)(CBK - 3) * e;
        float inv = 1.0f / Z;
        scoef[0] = (w0 - e) * inv;
        scoef[1] = (w1 - e) * inv;
        scoef[2] = (w2 - e) * inv;
        scoef[3] = e * inv;
        sidx[0] = cands[o0]; sidx[1] = cands[o1]; sidx[2] = cands[o2];
    }
    __syncthreads();
    out[(size_t)row * DIM + d] =
        scoef[0] * cb[(size_t)sidx[0] * DIM + d] +
        scoef[1] * cb[(size_t)sidx[1] * DIM + d] +
        scoef[2] * cb[(size_t)sidx[2] * DIM + d] +
        scoef[3] * g_S[d];
}

// ---------------------------------------------------------------------------
// launch
// ---------------------------------------------------------------------------
extern "C" void kernel_launch(void* const* d_in, const int* in_sizes, int n_in,
                              void* d_out, int out_size) {
    const float* x  = (const float*)d_in[0];   // [8192, 128]
    const float* cb = (const float*)d_in[1];   // [16384, 128]
    float* out = (float*)d_out;                // [8192, 128]

    prep_cb<<<128, 256>>>(cb);
    prep_x<<<64, 256>>>(x);
    colsum_final<<<1, 128>>>();

    cudaFuncSetAttribute(metoken_mma,
                         cudaFuncAttributeMaxDynamicSharedMemorySize, SM_TOTAL);
    metoken_mma<<<N_ROWS / BM, 256, SM_TOTAL>>>();

    epilogue<<<N_ROWS, 128>>>(x, cb, out);
}

// round 13
// speedup vs baseline: 3.0291x; 1.5191x over previous
#include <cuda_runtime.h>
#include <cuda_bf16.h>
#include <cstdint>

// ---------------- problem constants ----------------
#define N_ROWS 8192
#define DIM    128
#define CBK    16384
#define TAU    0.01f

#define BM     64            // rows per CTA
#define NT     128           // col tiles (16384 / 128)
#define TILE_N 128

// smem layout (bytes): x tile + 3-stage cb ring
#define XS_OFF 0             // 64 x 256B  = 16384
#define CB_OFF 16384         // 3 x 32768  = 98304
#define SM_TOTAL 114688

// ---------------- device scratch (no cudaMalloc allowed) ----------------
__device__ __nv_bfloat16 g_xh[(size_t)N_ROWS * DIM];
__device__ __nv_bfloat16 g_cbh[(size_t)CBK * DIM];
__device__ float g_Spart[128 * DIM];
__device__ float g_S[DIM];
__device__ int   g_candi[(size_t)N_ROWS * 64];

// ---------------- helpers ----------------
__device__ __forceinline__ uint32_t smem_u32(const void* p) {
    uint32_t a;
    asm("{ .reg .u64 t; cvta.to.shared.u64 t, %1; cvt.u32.u64 %0, t; }" : "=r"(a) : "l"(p));
    return a;
}
__device__ __forceinline__ void cp16(uint32_t dst, const void* src) {
    asm volatile("cp.async.cg.shared.global [%0], [%1], 16;" :: "r"(dst), "l"(src));
}
#define CP_COMMIT() asm volatile("cp.async.commit_group;" ::: "memory")
#define CP_WAIT2()  asm volatile("cp.async.wait_group 2;" ::: "memory")
#define CP_WAIT1()  asm volatile("cp.async.wait_group 1;" ::: "memory")
#define CP_WAIT0()  asm volatile("cp.async.wait_group 0;" ::: "memory")

__device__ __forceinline__ void ldsm_x4(uint32_t* r, uint32_t addr) {
    asm volatile("ldmatrix.sync.aligned.m8n8.x4.shared.b16 {%0,%1,%2,%3}, [%4];"
                 : "=r"(r[0]), "=r"(r[1]), "=r"(r[2]), "=r"(r[3]) : "r"(addr));
}
__device__ __forceinline__ void mma_bf16(float* c, const uint32_t* a, const uint32_t* b) {
    asm volatile(
        "mma.sync.aligned.m16n8k16.row.col.f32.bf16.bf16.f32 "
        "{%0,%1,%2,%3}, {%4,%5,%6,%7}, {%8,%9}, {%0,%1,%2,%3};"
        : "+f"(c[0]), "+f"(c[1]), "+f"(c[2]), "+f"(c[3])
        : "r"(a[0]), "r"(a[1]), "r"(a[2]), "r"(a[3]), "r"(b[0]), "r"(b[1]));
}

// ---------------------------------------------------------------------------
// prep: bf16 casts + codebook column sums
// ---------------------------------------------------------------------------
__global__ void __launch_bounds__(256) prep_cb(const float* __restrict__ cb) {
    int b = blockIdx.x;                 // 128 blocks x 128 rows
    int tid = threadIdx.x;
    const float* src = cb + (size_t)b * 128 * DIM;
    for (int e = tid; e < 128 * DIM; e += 256)
        g_cbh[(size_t)b * 128 * DIM + e] = __float2bfloat16(src[e]);
    __shared__ float ssum[256];
    int d = tid & 127, half = tid >> 7;
    float s = 0.0f;
#pragma unroll 8
    for (int r = half * 64; r < half * 64 + 64; ++r) s += src[r * DIM + d];
    ssum[tid] = s;
    __syncthreads();
    if (tid < 128) g_Spart[b * DIM + tid] = ssum[tid] + ssum[128 + tid];
}

__global__ void __launch_bounds__(256) prep_x(const float* __restrict__ x) {
    size_t base = (size_t)blockIdx.x * 128 * DIM;   // 64 blocks x 128 rows
    for (int e = threadIdx.x; e < 128 * DIM; e += 256)
        g_xh[base + e] = __float2bfloat16(x[base + e]);
}

__global__ void colsum_final() {
    int d = threadIdx.x;
    float s = 0.0f;
#pragma unroll 8
    for (int b = 0; b < 128; ++b) s += g_Spart[b * DIM + d];
    g_S[d] = s;
}

// ---------------------------------------------------------------------------
// cb tile loader: 2048 x 16B chunks, XOR-swizzled rows (256B/row)
// ---------------------------------------------------------------------------
__device__ __forceinline__ void load_cb_tile(int tile, int stage, int tid, uint32_t sbase) {
    const __nv_bfloat16* src0 = g_cbh + (size_t)tile * TILE_N * DIM;
    uint32_t dst0 = sbase + CB_OFF + (uint32_t)stage * 32768u;
#pragma unroll
    for (int k = 0; k < 8; ++k) {
        int c = tid + k * 256;          // 0..2047
        int n = c >> 4, kc = c & 15;
        cp16(dst0 + (uint32_t)(n * 256 + (((kc ^ (n & 7))) << 4)),
             src0 + (size_t)n * DIM + kc * 8);
    }
}

// ---------------------------------------------------------------------------
// main: bf16 mma.sync scores GEMM + in-register per-(thread,row) top-4
// ---------------------------------------------------------------------------
__global__ void __launch_bounds__(256, 1) metoken_mma() {
    extern __shared__ char smem[];
    uint32_t sbase = smem_u32(smem);

    const int tid = threadIdx.x, warp = tid >> 5, lane = tid & 31;
    const int wm = warp >> 2, wn = warp & 3;
    const int rowbase = blockIdx.x * BM;

    // ---- prologue loads: x tile (group0) + first two cb tiles ----
#pragma unroll
    for (int k = 0; k < 4; ++k) {
        int c = tid + k * 256;          // 0..1023
        int r = c >> 4, kc = c & 15;
        cp16(sbase + XS_OFF + (uint32_t)(r * 256 + ((kc ^ (r & 7)) << 4)),
             g_xh + (size_t)(rowbase + r) * DIM + kc * 8);
    }
    CP_COMMIT();
    load_cb_tile(0, 0, tid, sbase); CP_COMMIT();
    load_cb_tile(1, 1, tid, sbase); CP_COMMIT();
    CP_WAIT2();                          // own x-parts complete
    __syncthreads();                     // x visible to all

    // ---- hoist A fragments for the whole kernel (K=128, M=32 per warp) ----
    const int arow0 = wm * 32 + ((lane >> 3) & 1) * 8 + (lane & 7);
    const int ahi   = (lane >> 4) & 1;
    const int swa   = arow0 & 7;
    uint32_t ra[2][8][4];
#pragma unroll
    for (int mt = 0; mt < 2; ++mt)
#pragma unroll
        for (int kt = 0; kt < 8; ++kt)
            ldsm_x4(ra[mt][kt],
                    sbase + XS_OFF + (uint32_t)((arow0 + mt * 16) * 256 +
                                                (((kt * 2 + ahi) ^ swa) << 4)));

    // B lane constants
    const int bn0 = wn * 32 + ((lane >> 4) & 1) * 8 + (lane & 7);
    const int bhi = (lane >> 3) & 1;
    const int swb = bn0 & 7;

    // per-(thread,row) sorted top-4 lists; list li = mt*2 + h
    float lv[4][4]; int lid[4][4];
#pragma unroll
    for (int li = 0; li < 4; ++li)
#pragma unroll
        for (int k = 0; k < 4; ++k) { lv[li][k] = -3.4e38f; lid[li][k] = 0; }

    const int cbase = wn * 32 + 2 * (lane & 3);   // col offset of e=0 within tile

    for (int i = 0; i < NT; ++i) {
        // own groups for tile i complete (allow tiles i+1, i+2... only i+1 pending)
        if (i + 2 < NT) { CP_WAIT1(); } else { CP_WAIT0(); }
        __syncthreads();                 // tile i visible; tile i-1 reads done

        if (i + 2 < NT) { load_cb_tile(i + 2, (i + 2) % 3, tid, sbase); CP_COMMIT(); }

        uint32_t cbb = sbase + CB_OFF + (uint32_t)(i % 3) * 32768u;
        float acc[2][4][4];
#pragma unroll
        for (int mt = 0; mt < 2; ++mt)
#pragma unroll
            for (int nt = 0; nt < 4; ++nt)
#pragma unroll
                for (int e = 0; e < 4; ++e) acc[mt][nt][e] = 0.0f;

#pragma unroll
        for (int kt = 0; kt < 8; ++kt) {
            uint32_t rb[2][4];
#pragma unroll
            for (int g = 0; g < 2; ++g)
                ldsm_x4(rb[g], cbb + (uint32_t)((bn0 + g * 16) * 256 +
                                                (((kt * 2 + bhi) ^ swb) << 4)));
#pragma unroll
            for (int nt = 0; nt < 4; ++nt) {
                const uint32_t* bf = &rb[nt >> 1][(nt & 1) * 2];
#pragma unroll
                for (int mt = 0; mt < 2; ++mt)
                    mma_bf16(acc[mt][nt], ra[mt][kt], bf);
            }
        }

        // ---- in-register selection: fast row-max gate, rare sorted insert ----
        int colbase = i * 128 + cbase;
#pragma unroll
        for (int mt = 0; mt < 2; ++mt) {
#pragma unroll
            for (int h = 0; h < 2; ++h) {
                const int li = mt * 2 + h;
                float m = fmaxf(
                    fmaxf(fmaxf(acc[mt][0][2*h], acc[mt][0][2*h+1]),
                          fmaxf(acc[mt][1][2*h], acc[mt][1][2*h+1])),
                    fmaxf(fmaxf(acc[mt][2][2*h], acc[mt][2][2*h+1]),
                          fmaxf(acc[mt][3][2*h], acc[mt][3][2*h+1])));
                if (m > lv[li][3]) {
#pragma unroll
                    for (int nt = 0; nt < 4; ++nt) {
#pragma unroll
                        for (int e = 0; e < 2; ++e) {
                            float s = acc[mt][nt][2*h + e];
                            if (s > lv[li][3]) {
                                int c = colbase + nt * 8 + e;
                                if (s > lv[li][1]) {
                                    lv[li][3] = lv[li][2]; lid[li][3] = lid[li][2];
                                    lv[li][2] = lv[li][1]; lid[li][2] = lid[li][1];
                                    if (s > lv[li][0]) {
                                        lv[li][1] = lv[li][0]; lid[li][1] = lid[li][0];
                                        lv[li][0] = s;         lid[li][0] = c;
                                    } else { lv[li][1] = s;    lid[li][1] = c; }
                                } else {
                                    if (s > lv[li][2]) {
                                        lv[li][3] = lv[li][2]; lid[li][3] = lid[li][2];
                                        lv[li][2] = s;         lid[li][2] = c;
                                    } else { lv[li][3] = s;    lid[li][3] = c; }
                                }
                            }
                        }
                    }
                }
            }
        }
    }

    // ---- emit 4 candidates per (thread,row): 16 partitions x 4 = 64 per row ----
    const int pid = wn * 4 + (lane & 3);          // partition id within row
#pragma unroll
    for (int mt = 0; mt < 2; ++mt)
#pragma unroll
        for (int h = 0; h < 2; ++h) {
            const int li = mt * 2 + h;
            int row = rowbase + wm * 32 + mt * 16 + (lane >> 2) + 8 * h;
#pragma unroll
            for (int k = 0; k < 4; ++k)
                g_candi[(size_t)row * 64 + pid * 4 + k] = lid[li][k];
        }
}

// ---------------------------------------------------------------------------
// epilogue: exact fp32 rescore of 64 candidates, top-3, closed-form softmax
// ---------------------------------------------------------------------------
__global__ void __launch_bounds__(128) epilogue(const float* __restrict__ x,
                                                const float* __restrict__ cb,
                                                float* __restrict__ out) {
    int row = blockIdx.x;
    int d = threadIdx.x, w = d >> 5, lane = d & 31;
    __shared__ int   cands[64];
    __shared__ float ssc[64];
    __shared__ float scoef[4];
    __shared__ int   sidx[3];

    if (d < 64) cands[d] = g_candi[(size_t)row * 64 + d];
    __syncthreads();

    // warp w rescoares candidates 16w..16w+15 with float4 dots
    const float4* x4 = reinterpret_cast<const float4*>(x + (size_t)row * DIM);
    float4 xv = x4[lane];
#pragma unroll
    for (int t = 0; t < 16; ++t) {
        int cand = cands[w * 16 + t];
        float4 cv = reinterpret_cast<const float4*>(cb + (size_t)cand * DIM)[lane];
        float p = xv.x * cv.x + xv.y * cv.y + xv.z * cv.z + xv.w * cv.w;
#pragma unroll
        for (int o = 16; o > 0; o >>= 1) p += __shfl_xor_sync(0xffffffff, p, o);
        if (lane == 0) ssc[w * 16 + t] = p;
    }
    __syncthreads();
    if (d == 0) {
        float b0 = -3.4e38f, b1 = -3.4e38f, b2 = -3.4e38f;
        int   o0 = 0, o1 = 0, o2 = 0;
        for (int j = 0; j < 64; ++j) {
            float s = ssc[j];
            if (s > b2) {
                if (s > b1) {
                    b2 = b1; o2 = o1;
                    if (s > b0) { b1 = b0; o1 = o0; b0 = s; o0 = j; }
                    else        { b1 = s;  o1 = j; }
                } else { b2 = s; o2 = j; }
            }
        }
        float a0 = b0 / TAU, a1 = b1 / TAU, a2 = b2 / TAU;
        float M  = fmaxf(a0, 0.0f);
        float w0 = expf(a0 - M), w1 = expf(a1 - M), w2 = expf(a2 - M);
        float e  = expf(-M);
        float Z  = w0 + w1 + w2 + (float)(CBK - 3) * e;
        float inv = 1.0f / Z;
        scoef[0] = (w0 - e) * inv;
        scoef[1] = (w1 - e) * inv;
        scoef[2] = (w2 - e) * inv;
        scoef[3] = e * inv;
        sidx[0] = cands[o0]; sidx[1] = cands[o1]; sidx[2] = cands[o2];
    }
    __syncthreads();
    out[(size_t)row * DIM + d] =
        scoef[0] * cb[(size_t)sidx[0] * DIM + d] +
        scoef[1] * cb[(size_t)sidx[1] * DIM + d] +
        scoef[2] * cb[(size_t)sidx[2] * DIM + d] +
        scoef[3] * g_S[d];
}

// ---------------------------------------------------------------------------
// launch
// ---------------------------------------------------------------------------
extern "C" void kernel_launch(void* const* d_in, const int* in_sizes, int n_in,
                              void* d_out, int out_size) {
    const float* x  = (const float*)d_in[0];   // [8192, 128]
    const float* cb = (const float*)d_in[1];   // [16384, 128]
    float* out = (float*)d_out;                // [8192, 128]

    prep_cb<<<128, 256>>>(cb);
    prep_x<<<64, 256>>>(x);
    colsum_final<<<1, 128>>>();

    cudaFuncSetAttribute(metoken_mma,
                         cudaFuncAttributeMaxDynamicSharedMemorySize, SM_TOTAL);
    metoken_mma<<<N_ROWS / BM, 256, SM_TOTAL>>>();

    epilogue<<<N_ROWS, 128>>>(x, cb, out);
}